// round 16
// baseline (speedup 1.0000x reference)
#include <cuda_runtime.h>
#include <cuda_fp16.h>
#include <cstdint>

#define T_TOK 8192
#define DIM   1024
#define HID   2752
#define NE    8
#define TOPK  2

#define BM 128
#define BN 128
#define BK 64                            // halves per k-iter (128B rows)
#define TILE_B (BM * 128)                // 16384 B per matrix tile
#define ST2 (2 * TILE_B)                 // stage: A + B = 32768 B

#define STASH_OFF (2 * ST2)              // 65536: 32KB silu(G) stash
#define TOK_OFF   (2 * ST2 + 32768)      // 98304
#define SMEMF     (TOK_OFF + 512)        // 98816 (2 CTAs/SM)
#define SMEM2     (3 * ST2)              // ffn2: 3-stage, 98304 (2 CTAs/SM)

#define NT1 ((HID + BN - 1) / BN)        // 22
#define NT2 (DIM / BN)                   // 8
#define NIT1 (DIM / BK)                  // 16
#define NIT2 (HID / BK)                  // 43

#define NROWS (T_TOK * TOPK + T_TOK)     // 24576 rows in h buffer

// w2/sw2 deferred conversion (done by ffn1's idle CTAs)
#define W2N4   (NE * DIM * HID / 4)      // 5767168 float4s
#define S2N4   (DIM * HID / 4)           // 720896
#define TOT4   (W2N4 + S2N4)             // 6488064
#define NCHUNK 8000                      // idle CTAs guaranteed >= 8272
#define CHUNK  ((TOT4 + NCHUNK - 1) / NCHUNK)  // 812

#define SWZ(r, c) ((r) * 128 + ((((c) ^ ((r) & 7))) * 16))

// ---------------- device scratch ------------------------------------------------
__device__ int   g_counts[NE];
__device__ int   g_offsets[NE + 1];
__device__ int   g_fill[NE];
__device__ int   g_ticket;
__device__ int   g_topk_idx[T_TOK * TOPK];
__device__ float g_topk_w[T_TOK * TOPK];
__device__ int   g_perm[T_TOK * TOPK];
__device__ float g_coef[T_TOK * TOPK];
__device__ __half g_xh[(size_t)T_TOK * DIM];
__device__ __half g_w1h[(size_t)NE * HID * DIM];
__device__ __half g_w3h[(size_t)NE * HID * DIM];
__device__ __half g_w2h[(size_t)NE * DIM * HID];
__device__ __half g_sw1h[(size_t)HID * DIM];
__device__ __half g_sw3h[(size_t)HID * DIM];
__device__ __half g_sw2h[(size_t)DIM * HID];
__device__ __half g_h[(size_t)NROWS * HID];   // silu(G)*U

// ---------------- helpers --------------------------------------------------------
__device__ __forceinline__ uint32_t smem_u32(const void* p) {
    return (uint32_t)__cvta_generic_to_shared(p);
}
__device__ __forceinline__ void cp16(uint32_t dst, const void* src) {
    asm volatile("cp.async.cg.shared.global [%0], [%1], 16;\n" :: "r"(dst), "l"(src));
}
__device__ __forceinline__ void cp_commit() { asm volatile("cp.async.commit_group;\n"); }
template <int N>
__device__ __forceinline__ void cp_wait() { asm volatile("cp.async.wait_group %0;\n" :: "n"(N)); }

__device__ __forceinline__ void ldm_x4(uint32_t* r, uint32_t addr) {
    asm volatile("ldmatrix.sync.aligned.m8n8.x4.shared.b16 {%0,%1,%2,%3}, [%4];"
                 : "=r"(r[0]), "=r"(r[1]), "=r"(r[2]), "=r"(r[3]) : "r"(addr));
}
__device__ __forceinline__ void ldm_x2(uint32_t* r, uint32_t addr) {
    asm volatile("ldmatrix.sync.aligned.m8n8.x2.shared.b16 {%0,%1}, [%2];"
                 : "=r"(r[0]), "=r"(r[1]) : "r"(addr));
}
__device__ __forceinline__ void mma_f16(float* d, const uint32_t* a, const uint32_t* b) {
    asm volatile(
        "mma.sync.aligned.m16n8k16.row.col.f32.f16.f16.f32 "
        "{%0,%1,%2,%3},{%4,%5,%6,%7},{%8,%9},{%0,%1,%2,%3};\n"
        : "+f"(d[0]), "+f"(d[1]), "+f"(d[2]), "+f"(d[3])
        : "r"(a[0]), "r"(a[1]), "r"(a[2]), "r"(a[3]), "r"(b[0]), "r"(b[1]));
}
__device__ __forceinline__ uint2 cvt_f4(float4 v) {
    __half2 lo = __floats2half2_rn(v.x, v.y);
    __half2 hi = __floats2half2_rn(v.z, v.w);
    uint2 o;
    o.x = *(uint32_t*)&lo;
    o.y = *(uint32_t*)&hi;
    return o;
}

// ---------------- kernel 0: init counters ------------------------------------------
__global__ void init_kernel() {
    if (threadIdx.x < NE) { g_counts[threadIdx.x] = 0; g_fill[threadIdx.x] = 0; }
    if (threadIdx.x == 0) g_ticket = 0;
}

// ---------------- kernel 1: fused convert (5 tensors) + gate ------------------------
// (w2/sw2 conversion is deferred to ffn1's idle CTAs)
struct CvtArgs {
    const float4* src[5];
    uint2*        dst[5];
    int           n4[5];
};
#define GATE_BLKS (T_TOK / 8)   // 1024
#define CVT_BLKS  4096
__global__ void cvt_gate_kernel(CvtArgs a, const float* __restrict__ x,
                                const float* __restrict__ gw) {
    const int bid = blockIdx.x;
    if (bid < GATE_BLKS) {
        int warp = threadIdx.x >> 5, lane = threadIdx.x & 31;
        int t = bid * 8 + warp;
        const float* xr = x + (size_t)t * DIM;
        float acc[NE];
#pragma unroll
        for (int e = 0; e < NE; e++) acc[e] = 0.f;
        for (int k = lane; k < DIM; k += 32) {
            float xv = xr[k];
#pragma unroll
            for (int e = 0; e < NE; e++) acc[e] += xv * gw[e * DIM + k];
        }
#pragma unroll
        for (int e = 0; e < NE; e++)
#pragma unroll
            for (int o = 16; o > 0; o >>= 1) acc[e] += __shfl_xor_sync(0xffffffffu, acc[e], o);
        if (lane == 0) {
            float mx = acc[0];
#pragma unroll
            for (int e = 1; e < NE; e++) mx = fmaxf(mx, acc[e]);
            float p[NE], s = 0.f;
#pragma unroll
            for (int e = 0; e < NE; e++) { p[e] = expf(acc[e] - mx); s += p[e]; }
            float inv = 1.f / s;
#pragma unroll
            for (int e = 0; e < NE; e++) p[e] *= inv;
            int i0 = 0; float b0 = p[0];
#pragma unroll
            for (int e = 1; e < NE; e++) if (p[e] > b0) { b0 = p[e]; i0 = e; }
            int i1 = -1; float b1 = -1.f;
#pragma unroll
            for (int e = 0; e < NE; e++) if (e != i0 && p[e] > b1) { b1 = p[e]; i1 = e; }
            float wn = 1.f / (b0 + b1 + 1e-20f);
            g_topk_idx[2 * t] = i0;     g_topk_idx[2 * t + 1] = i1;
            g_topk_w[2 * t] = b0 * wn;  g_topk_w[2 * t + 1] = b1 * wn;
            atomicAdd(&g_counts[i0], 1);
            atomicAdd(&g_counts[i1], 1);
        }
        return;
    }
    const int stride = CVT_BLKS * blockDim.x;
    const int t0 = (bid - GATE_BLKS) * blockDim.x + threadIdx.x;
#pragma unroll
    for (int s = 0; s < 5; s++) {
        const float4* __restrict__ src = a.src[s];
        uint2* __restrict__ dst = a.dst[s];
        const int n = a.n4[s];
        for (int i = t0; i < n; i += stride) dst[i] = cvt_f4(src[i]);
    }
}

// ---------------- kernel 2: scatter (computes offsets locally) ----------------------
__global__ void scatter_kernel() {
    int off[NE];
    {
        int o = 0;
#pragma unroll
        for (int e = 0; e < NE; e++) { off[e] = o; o += g_counts[e]; }
        if (blockIdx.x == 0 && threadIdx.x == 0) {
#pragma unroll
            for (int e = 0; e < NE; e++) g_offsets[e] = off[e];
            g_offsets[NE] = o;
        }
    }
    int t = blockIdx.x * blockDim.x + threadIdx.x;
    if (t >= T_TOK) return;
#pragma unroll
    for (int k = 0; k < TOPK; k++) {
        int e = g_topk_idx[2 * t + k];
        int pos = off[e] + atomicAdd(&g_fill[e], 1);
        g_perm[pos] = t;
        g_coef[pos] = g_topk_w[2 * t + k];
    }
}

// ---------------- kernel 3: FFN1 — h = silu(X W1^T) * (X W3^T), R12-proven ----------
// Two sequential 2-stage K-loops (W1 then W3); silu(G) stashed in SMEM between.
// Idle CTAs (m0 >= rows) convert w2/sw2 to fp16 instead of returning.
__global__ __launch_bounds__(256, 2) void ffn1_kernel(const float4* __restrict__ w2src,
                                                      uint2* __restrict__ w2dst,
                                                      const float4* __restrict__ s2src,
                                                      uint2* __restrict__ s2dst) {
    extern __shared__ char smem[];
    const uint32_t sbase = smem_u32(smem);
    const int seg = blockIdx.z;
    const int rows = (seg < NE) ? g_counts[seg] : T_TOK;
    const int m0 = blockIdx.y * BM;
    const int tid = threadIdx.x;
    if (m0 >= rows) {
        // idle CTA: convert one chunk of w2/sw2 (overlaps with active CTAs' GEMMs)
        __shared__ int s_t;
        if (tid == 0) s_t = atomicAdd(&g_ticket, 1);
        __syncthreads();
        const int t = s_t;
        if (t >= NCHUNK) return;
        const int s = t * CHUNK;
        const int e = min(s + CHUNK, (int)TOT4);
        for (int i = s + tid; i < e; i += 256) {
            if (i < W2N4) w2dst[i] = cvt_f4(w2src[i]);
            else          s2dst[i - W2N4] = cvt_f4(s2src[i - W2N4]);
        }
        return;
    }
    const int segoff = (seg < NE) ? g_offsets[seg] : 0;
    const size_t hbase = (seg < NE) ? (size_t)g_offsets[seg] : (size_t)(T_TOK * TOPK);
    const __half* W1 = (seg < NE) ? g_w1h + (size_t)seg * HID * DIM : g_sw1h;
    const __half* W3 = (seg < NE) ? g_w3h + (size_t)seg * HID * DIM : g_sw3h;
    const int n0 = blockIdx.x * BN;

    int* stok = (int*)(smem + TOK_OFF);
    if (tid < BM) {
        int r = m0 + tid;
        int rr = (r < rows) ? r : m0;
        stok[tid] = (seg < NE) ? g_perm[segoff + rr] : rr;
    }
    __syncthreads();

    const __half* aptr[4];
    uint32_t boff[4], sdst[4];
#pragma unroll
    for (int i = 0; i < 4; i++) {
        int j = tid + i * 256;
        int r = j >> 3, c8 = j & 7;
        sdst[i] = SWZ(r, c8);
        aptr[i] = g_xh + (size_t)stok[r] * DIM + c8 * 8;
        int nn = n0 + r; if (nn >= HID) nn = HID - 1;
        boff[i] = (uint32_t)nn * DIM + c8 * 8;
    }
    auto loadAll = [&](const __half* W, int it, int buf) {
        const uint32_t base = sbase + buf * ST2;
        const int kt = it * BK;
#pragma unroll
        for (int i = 0; i < 4; i++) {
            cp16(base + sdst[i],          aptr[i] + kt);
            cp16(base + TILE_B + sdst[i], W + boff[i] + kt);
        }
    };

    const int lane = tid & 31, wid = tid >> 5;
    const int wm = wid & 1, wn = wid >> 1;
    const int g = lane >> 2, tg = lane & 3;

    const uint32_t a_roff = (uint32_t)(wm * 64 + (lane & 15)) * 128;
    const uint32_t a_x = lane & 7, a_c = (uint32_t)(lane >> 4);
    const uint32_t b_roff = (uint32_t)(wn * 32 + (lane & 7)) * 128;
    const uint32_t b_c = (uint32_t)((lane >> 3) & 1);

    uint32_t achs[4], bchs[4];
#pragma unroll
    for (int kk = 0; kk < 4; kk++) {
        achs[kk] = ((kk * 2 + a_c) ^ a_x) * 16;
        bchs[kk] = ((kk * 2 + b_c) ^ a_x) * 16;
    }

    float acc[4][4][4];
#pragma unroll
    for (int a = 0; a < 4; a++)
#pragma unroll
        for (int b = 0; b < 4; b++)
#pragma unroll
            for (int c = 0; c < 4; c++) acc[a][b][c] = 0.f;

    // stash addressing: per-thread private, uint32 value v at word [v*256 + tid]
    const uint32_t stash = sbase + STASH_OFF + tid * 4;

    // ---------------- loop 1: G = X W1^T ----------------
    loadAll(W1, 0, 0); cp_commit();
    for (int it = 0; it < NIT1; ++it) {
        const int buf = it & 1;
        if (it + 1 < NIT1) { loadAll(W1, it + 1, buf ^ 1); cp_commit(); cp_wait<1>(); }
        else               { cp_wait<0>(); }
        __syncthreads();
        const uint32_t aB = sbase + buf * ST2;
        const uint32_t bB = aB + TILE_B;
#pragma unroll
        for (int kk = 0; kk < 4; kk++) {
            uint32_t af[4][4];
#pragma unroll
            for (int mi = 0; mi < 4; mi++)
                ldm_x4(af[mi], aB + a_roff + mi * 2048 + achs[kk]);
#pragma unroll
            for (int ni = 0; ni < 4; ni++) {
                uint32_t bf[2];
                ldm_x2(bf, bB + b_roff + ni * 1024 + bchs[kk]);
#pragma unroll
                for (int mi = 0; mi < 4; mi++) mma_f16(acc[mi][ni], af[mi], bf);
            }
        }
        __syncthreads();   // 2-stage: protect buf^1 before next-iter overwrite
    }

    // prime loop2's first tile BEFORE the stash epilogue (hides load latency)
    loadAll(W3, 0, 0); cp_commit();

    // epilogue 1: silu(G) -> SMEM stash (per-thread private; no barrier needed)
#pragma unroll
    for (int mi = 0; mi < 4; mi++)
#pragma unroll
        for (int ni = 0; ni < 4; ni++)
#pragma unroll
            for (int rh = 0; rh < 2; rh++) {
                float g0 = acc[mi][ni][rh * 2], g1 = acc[mi][ni][rh * 2 + 1];
                float s0 = g0 / (1.f + expf(-g0));
                float s1 = g1 / (1.f + expf(-g1));
                __half2 sv = __floats2half2_rn(s0, s1);
                const int v = (mi * 4 + ni) * 2 + rh;
                asm volatile("st.shared.b32 [%0], %1;" :: "r"(stash + v * 1024),
                             "r"(*(uint32_t*)&sv));
            }

#pragma unroll
    for (int a = 0; a < 4; a++)
#pragma unroll
        for (int b = 0; b < 4; b++)
#pragma unroll
            for (int c = 0; c < 4; c++) acc[a][b][c] = 0.f;

    // ---------------- loop 2: U = X W3^T ----------------
    for (int it = 0; it < NIT1; ++it) {
        const int buf = it & 1;
        if (it + 1 < NIT1) { loadAll(W3, it + 1, buf ^ 1); cp_commit(); cp_wait<1>(); }
        else               { cp_wait<0>(); }
        __syncthreads();
        const uint32_t aB = sbase + buf * ST2;
        const uint32_t bB = aB + TILE_B;
#pragma unroll
        for (int kk = 0; kk < 4; kk++) {
            uint32_t af[4][4];
#pragma unroll
            for (int mi = 0; mi < 4; mi++)
                ldm_x4(af[mi], aB + a_roff + mi * 2048 + achs[kk]);
#pragma unroll
            for (int ni = 0; ni < 4; ni++) {
                uint32_t bf[2];
                ldm_x2(bf, bB + b_roff + ni * 1024 + bchs[kk]);
#pragma unroll
                for (int mi = 0; mi < 4; mi++) mma_f16(acc[mi][ni], af[mi], bf);
            }
        }
        __syncthreads();
    }

    // epilogue 2: h = stash(silu G) * U -> g_h (fp16)
#pragma unroll
    for (int mi = 0; mi < 4; mi++) {
#pragma unroll
        for (int rh = 0; rh < 2; rh++) {
            const int rr = m0 + wm * 64 + mi * 16 + g + rh * 8;
            if (rr >= rows) continue;
            __half* drow = g_h + (hbase + rr) * (size_t)HID;
#pragma unroll
            for (int ni = 0; ni < 4; ni++) {
                const int c = n0 + wn * 32 + ni * 8 + 2 * tg;
                if (c >= HID) continue;
                const int v = (mi * 4 + ni) * 2 + rh;
                uint32_t sbits;
                asm volatile("ld.shared.b32 %0, [%1];" : "=r"(sbits)
                             : "r"(stash + v * 1024));
                float2 sv = __half22float2(*(__half2*)&sbits);
                float h0 = sv.x * acc[mi][ni][rh * 2];
                float h1 = sv.y * acc[mi][ni][rh * 2 + 1];
                __half2 hv = __floats2half2_rn(h0, h1);
                *(uint32_t*)(drow + c) = *(uint32_t*)&hv;
            }
        }
    }
}

// ---------------- kernels 4/5: FFN2 — out (+)= coef * (h W2^T) --------------------------
template <bool SHARED>
__global__ __launch_bounds__(256, 2) void ffn2_kernel(float* __restrict__ out) {
    extern __shared__ char smem[];
    const uint32_t sbase = smem_u32(smem);
    const int z = SHARED ? NE : blockIdx.z;
    const int rows = SHARED ? T_TOK : g_counts[z];
    const int m0 = blockIdx.y * BM;
    if (m0 >= rows) return;
    const int segoff = SHARED ? 0 : g_offsets[z];
    const size_t hbase = SHARED ? (size_t)(T_TOK * TOPK) : (size_t)g_offsets[z];
    const __half* W2 = SHARED ? g_sw2h : g_w2h + (size_t)z * DIM * HID;
    const int n0 = blockIdx.x * BN;
    const int tid = threadIdx.x;

    const __half* aptr[4];
    const __half* bptr[4];
    uint32_t sdst[4];
#pragma unroll
    for (int i = 0; i < 4; i++) {
        int j = tid + i * 256;
        int r = j >> 3, c8 = j & 7;
        sdst[i] = SWZ(r, c8);
        int rr = (m0 + r < rows) ? (m0 + r) : m0;
        aptr[i] = g_h + (hbase + rr) * (size_t)HID + c8 * 8;
        bptr[i] = W2 + (size_t)(n0 + r) * HID + c8 * 8;
    }
    auto loadAll = [&](int it, int stg) {
        const uint32_t base = sbase + stg * ST2;
        const int kt = it * BK;
#pragma unroll
        for (int i = 0; i < 4; i++) {
            cp16(base + sdst[i],          aptr[i] + kt);
            cp16(base + TILE_B + sdst[i], bptr[i] + kt);
        }
    };

    const int lane = tid & 31, wid = tid >> 5;
    const int wm = wid & 1, wn = wid >> 1;
    const int g = lane >> 2, tg = lane & 3;

    const uint32_t a_roff = (uint32_t)(wm * 64 + (lane & 15)) * 128;
    const uint32_t a_x = lane & 7, a_c = (uint32_t)(lane >> 4);
    const uint32_t b_roff = (uint32_t)(wn * 32 + (lane & 7)) * 128;
    const uint32_t b_c = (uint32_t)((lane >> 3) & 1);

    uint32_t achs[4], bchs[4];
#pragma unroll
    for (int kk = 0; kk < 4; kk++) {
        achs[kk] = ((kk * 2 + a_c) ^ a_x) * 16;
        bchs[kk] = ((kk * 2 + b_c) ^ a_x) * 16;
    }

    float acc[4][4][4];
#pragma unroll
    for (int a = 0; a < 4; a++)
#pragma unroll
        for (int b = 0; b < 4; b++)
#pragma unroll
            for (int c = 0; c < 4; c++) acc[a][b][c] = 0.f;

    loadAll(0, 0); cp_commit();
    loadAll(1, 1); cp_commit();
    for (int it = 0; it < NIT2; ++it) {
        const int stg = it % 3;
        if (it + 1 < NIT2) cp_wait<1>(); else cp_wait<0>();
        __syncthreads();
        if (it + 2 < NIT2) { loadAll(it + 2, (it + 2) % 3); cp_commit(); }
        const uint32_t aB = sbase + stg * ST2;
        const uint32_t bB = aB + TILE_B;
#pragma unroll
        for (int kk = 0; kk < 4; kk++) {
            uint32_t af[4][4];
#pragma unroll
            for (int mi = 0; mi < 4; mi++)
                ldm_x4(af[mi], aB + a_roff + mi * 2048 + achs[kk]);
#pragma unroll
            for (int ni = 0; ni < 4; ni++) {
                uint32_t bf[2];
                ldm_x2(bf, bB + b_roff + ni * 1024 + bchs[kk]);
#pragma unroll
                for (int mi = 0; mi < 4; mi++) mma_f16(acc[mi][ni], af[mi], bf);
            }
        }
    }

    // epilogue
#pragma unroll
    for (int mi = 0; mi < 4; mi++) {
#pragma unroll
        for (int rh = 0; rh < 2; rh++) {
            const int rr = m0 + wm * 64 + mi * 16 + g + rh * 8;
            if (!SHARED && rr >= rows) continue;
            const int   tok = SHARED ? rr : g_perm[segoff + rr];
            const float cf  = SHARED ? 1.f : g_coef[segoff + rr];
            float* orow = out + (size_t)tok * DIM;
#pragma unroll
            for (int ni = 0; ni < 4; ni++) {
                const int c = n0 + wn * 32 + ni * 8 + 2 * tg;
                if (SHARED) {
                    orow[c]     = acc[mi][ni][rh * 2];
                    orow[c + 1] = acc[mi][ni][rh * 2 + 1];
                } else {
                    atomicAdd(&orow[c],     cf * acc[mi][ni][rh * 2]);
                    atomicAdd(&orow[c + 1], cf * acc[mi][ni][rh * 2 + 1]);
                }
            }
        }
    }
}

// ---------------- launcher -------------------------------------------------------------------
extern "C" void kernel_launch(void* const* d_in, const int* in_sizes, int n_in,
                              void* d_out, int out_size) {
    const float* x   = (const float*)d_in[0];
    const float* gw  = (const float*)d_in[1];
    const float* w1  = (const float*)d_in[2];
    const float* w2  = (const float*)d_in[3];
    const float* w3  = (const float*)d_in[4];
    const float* sw1 = (const float*)d_in[5];
    const float* sw2 = (const float*)d_in[6];
    const float* sw3 = (const float*)d_in[7];
    float* out = (float*)d_out;

    cudaFuncSetAttribute(ffn1_kernel, cudaFuncAttributeMaxDynamicSharedMemorySize, SMEMF);
    cudaFuncSetAttribute(ffn2_kernel<true>,  cudaFuncAttributeMaxDynamicSharedMemorySize, SMEM2);
    cudaFuncSetAttribute(ffn2_kernel<false>, cudaFuncAttributeMaxDynamicSharedMemorySize, SMEM2);

    CvtArgs ca;
    void* p;
    cudaGetSymbolAddress(&p, g_xh);   ca.dst[0] = (uint2*)p; ca.src[0] = (const float4*)x;   ca.n4[0] = (T_TOK * DIM) / 4;
    cudaGetSymbolAddress(&p, g_w1h);  ca.dst[1] = (uint2*)p; ca.src[1] = (const float4*)w1;  ca.n4[1] = (NE * HID * DIM) / 4;
    cudaGetSymbolAddress(&p, g_w3h);  ca.dst[2] = (uint2*)p; ca.src[2] = (const float4*)w3;  ca.n4[2] = (NE * HID * DIM) / 4;
    cudaGetSymbolAddress(&p, g_sw1h); ca.dst[3] = (uint2*)p; ca.src[3] = (const float4*)sw1; ca.n4[3] = (HID * DIM) / 4;
    cudaGetSymbolAddress(&p, g_sw3h); ca.dst[4] = (uint2*)p; ca.src[4] = (const float4*)sw3; ca.n4[4] = (HID * DIM) / 4;

    uint2 *w2h, *s2h;
    cudaGetSymbolAddress(&p, g_w2h);  w2h = (uint2*)p;
    cudaGetSymbolAddress(&p, g_sw2h); s2h = (uint2*)p;

    init_kernel<<<1, 32>>>();                                  // 1
    cvt_gate_kernel<<<GATE_BLKS + CVT_BLKS, 256>>>(ca, x, gw); // 2
    scatter_kernel<<<T_TOK / 256, 256>>>();                    // 3

    dim3 g1(NT1, T_TOK / BM, NE + 1);
    ffn1_kernel<<<g1, 256, SMEMF>>>((const float4*)w2, w2h,
                                    (const float4*)sw2, s2h);  // 4 (+deferred w2 cvt)
    dim3 g2s(NT2, T_TOK / BM, 1);
    ffn2_kernel<true><<<g2s, 256, SMEM2>>>(out);               // 5
    dim3 g2r(NT2, T_TOK / BM, NE);
    ffn2_kernel<false><<<g2r, 256, SMEM2>>>(out);              // 6
}

// round 17
// speedup vs baseline: 1.2158x; 1.2158x over previous
#include <cuda_runtime.h>
#include <cuda_fp16.h>
#include <cstdint>

#define T_TOK 8192
#define DIM   1024
#define HID   2752
#define NE    8
#define TOPK  2

#define BM 128
#define BN 128
#define BK 64                            // halves per k-iter (128B rows)
#define TILE_B (BM * 128)                // 16384 B per matrix tile
#define ST2 (2 * TILE_B)                 // stage: A + B = 32768 B

#define STASH_OFF (2 * ST2)              // 65536: 32KB silu(G) stash
#define TOK_OFF   (2 * ST2 + 32768)      // 98304
#define SMEMF     (TOK_OFF + 512)        // 98816 (2 CTAs/SM)
#define SMEM2     (3 * ST2)              // ffn2: 3-stage, 98304 (2 CTAs/SM)

#define NT1 ((HID + BN - 1) / BN)        // 22
#define NT2 (DIM / BN)                   // 8
#define NIT1 (DIM / BK)                  // 16
#define NIT2 (HID / BK)                  // 43

#define NROWS (T_TOK * TOPK + T_TOK)     // 24576 rows in h buffer

#define SWZ(r, c) ((r) * 128 + ((((c) ^ ((r) & 7))) * 16))

// ---------------- device scratch ------------------------------------------------
__device__ int   g_counts[NE];
__device__ int   g_offsets[NE + 1];
__device__ int   g_fill[NE];
__device__ int   g_topk_idx[T_TOK * TOPK];
__device__ float g_topk_w[T_TOK * TOPK];
__device__ int   g_perm[T_TOK * TOPK];
__device__ float g_coef[T_TOK * TOPK];
__device__ __half g_xh[(size_t)T_TOK * DIM];
__device__ __half g_w1h[(size_t)NE * HID * DIM];
__device__ __half g_w3h[(size_t)NE * HID * DIM];
__device__ __half g_w2h[(size_t)NE * DIM * HID];
__device__ __half g_sw1h[(size_t)HID * DIM];
__device__ __half g_sw3h[(size_t)HID * DIM];
__device__ __half g_sw2h[(size_t)DIM * HID];
__device__ __half g_h[(size_t)NROWS * HID];   // silu(G)*U

// ---------------- helpers --------------------------------------------------------
__device__ __forceinline__ uint32_t smem_u32(const void* p) {
    return (uint32_t)__cvta_generic_to_shared(p);
}
__device__ __forceinline__ void cp16(uint32_t dst, const void* src) {
    asm volatile("cp.async.cg.shared.global [%0], [%1], 16;\n" :: "r"(dst), "l"(src));
}
__device__ __forceinline__ void cp_commit() { asm volatile("cp.async.commit_group;\n"); }
template <int N>
__device__ __forceinline__ void cp_wait() { asm volatile("cp.async.wait_group %0;\n" :: "n"(N)); }

__device__ __forceinline__ void ldm_x4(uint32_t* r, uint32_t addr) {
    asm volatile("ldmatrix.sync.aligned.m8n8.x4.shared.b16 {%0,%1,%2,%3}, [%4];"
                 : "=r"(r[0]), "=r"(r[1]), "=r"(r[2]), "=r"(r[3]) : "r"(addr));
}
__device__ __forceinline__ void ldm_x2(uint32_t* r, uint32_t addr) {
    asm volatile("ldmatrix.sync.aligned.m8n8.x2.shared.b16 {%0,%1}, [%2];"
                 : "=r"(r[0]), "=r"(r[1]) : "r"(addr));
}
__device__ __forceinline__ void mma_f16(float* d, const uint32_t* a, const uint32_t* b) {
    asm volatile(
        "mma.sync.aligned.m16n8k16.row.col.f32.f16.f16.f32 "
        "{%0,%1,%2,%3},{%4,%5,%6,%7},{%8,%9},{%0,%1,%2,%3};\n"
        : "+f"(d[0]), "+f"(d[1]), "+f"(d[2]), "+f"(d[3])
        : "r"(a[0]), "r"(a[1]), "r"(a[2]), "r"(a[3]), "r"(b[0]), "r"(b[1]));
}
// streaming (evict-first) load/store for the one-shot convert pass
__device__ __forceinline__ float4 ldcs4(const float4* p) {
    float4 v;
    asm volatile("ld.global.cs.v4.f32 {%0,%1,%2,%3}, [%4];"
                 : "=f"(v.x), "=f"(v.y), "=f"(v.z), "=f"(v.w) : "l"(p));
    return v;
}
__device__ __forceinline__ void stcs2(uint2* p, uint2 v) {
    asm volatile("st.global.cs.v2.u32 [%0], {%1,%2};" :: "l"(p), "r"(v.x), "r"(v.y)
                 : "memory");
}

// ---------------- kernel 0: init counters ------------------------------------------
__global__ void init_kernel() {
    if (threadIdx.x < NE) { g_counts[threadIdx.x] = 0; g_fill[threadIdx.x] = 0; }
}

// ---------------- kernel 1: fused convert (7 tensors) + gate ------------------------
struct CvtArgs {
    const float4* src[7];
    uint2*        dst[7];
    int           n4[7];
};
#define GATE_BLKS (T_TOK / 8)   // 1024
#define CVT_BLKS  8192
__global__ void cvt_gate_kernel(CvtArgs a, const float* __restrict__ x,
                                const float* __restrict__ gw) {
    const int bid = blockIdx.x;
    if (bid < GATE_BLKS) {
        int warp = threadIdx.x >> 5, lane = threadIdx.x & 31;
        int t = bid * 8 + warp;
        const float* xr = x + (size_t)t * DIM;
        float acc[NE];
#pragma unroll
        for (int e = 0; e < NE; e++) acc[e] = 0.f;
        for (int k = lane; k < DIM; k += 32) {
            float xv = xr[k];
#pragma unroll
            for (int e = 0; e < NE; e++) acc[e] += xv * gw[e * DIM + k];
        }
#pragma unroll
        for (int e = 0; e < NE; e++)
#pragma unroll
            for (int o = 16; o > 0; o >>= 1) acc[e] += __shfl_xor_sync(0xffffffffu, acc[e], o);
        if (lane == 0) {
            float mx = acc[0];
#pragma unroll
            for (int e = 1; e < NE; e++) mx = fmaxf(mx, acc[e]);
            float p[NE], s = 0.f;
#pragma unroll
            for (int e = 0; e < NE; e++) { p[e] = expf(acc[e] - mx); s += p[e]; }
            float inv = 1.f / s;
#pragma unroll
            for (int e = 0; e < NE; e++) p[e] *= inv;
            int i0 = 0; float b0 = p[0];
#pragma unroll
            for (int e = 1; e < NE; e++) if (p[e] > b0) { b0 = p[e]; i0 = e; }
            int i1 = -1; float b1 = -1.f;
#pragma unroll
            for (int e = 0; e < NE; e++) if (e != i0 && p[e] > b1) { b1 = p[e]; i1 = e; }
            float wn = 1.f / (b0 + b1 + 1e-20f);
            g_topk_idx[2 * t] = i0;     g_topk_idx[2 * t + 1] = i1;
            g_topk_w[2 * t] = b0 * wn;  g_topk_w[2 * t + 1] = b1 * wn;
            atomicAdd(&g_counts[i0], 1);
            atomicAdd(&g_counts[i1], 1);
        }
        return;
    }
    const int stride = CVT_BLKS * blockDim.x;
    const int t0 = (bid - GATE_BLKS) * blockDim.x + threadIdx.x;
#pragma unroll
    for (int s = 0; s < 7; s++) {
        const float4* __restrict__ src = a.src[s];
        uint2* __restrict__ dst = a.dst[s];
        const int n = a.n4[s];
        for (int i = t0; i < n; i += stride) {
            float4 v = ldcs4(src + i);
            __half2 lo = __floats2half2_rn(v.x, v.y);
            __half2 hi = __floats2half2_rn(v.z, v.w);
            uint2 o;
            o.x = *(uint32_t*)&lo;
            o.y = *(uint32_t*)&hi;
            stcs2(dst + i, o);
        }
    }
}

// ---------------- kernel 2: scatter (computes offsets locally) ----------------------
__global__ void scatter_kernel() {
    int off[NE];
    {
        int o = 0;
#pragma unroll
        for (int e = 0; e < NE; e++) { off[e] = o; o += g_counts[e]; }
        if (blockIdx.x == 0 && threadIdx.x == 0) {
#pragma unroll
            for (int e = 0; e < NE; e++) g_offsets[e] = off[e];
            g_offsets[NE] = o;
        }
    }
    int t = blockIdx.x * blockDim.x + threadIdx.x;
    if (t >= T_TOK) return;
#pragma unroll
    for (int k = 0; k < TOPK; k++) {
        int e = g_topk_idx[2 * t + k];
        int pos = off[e] + atomicAdd(&g_fill[e], 1);
        g_perm[pos] = t;
        g_coef[pos] = g_topk_w[2 * t + k];
    }
}

// ---------------- kernel 3: FFN1 — h = silu(X W1^T) * (X W3^T), R12-proven ----------
// Two sequential 2-stage K-loops (W1 then W3); silu(G) stashed in SMEM between.
__global__ __launch_bounds__(256, 2) void ffn1_kernel() {
    extern __shared__ char smem[];
    const uint32_t sbase = smem_u32(smem);
    const int seg = blockIdx.z;
    const int rows = (seg < NE) ? g_counts[seg] : T_TOK;
    const int m0 = blockIdx.y * BM;
    if (m0 >= rows) return;
    const int segoff = (seg < NE) ? g_offsets[seg] : 0;
    const size_t hbase = (seg < NE) ? (size_t)g_offsets[seg] : (size_t)(T_TOK * TOPK);
    const __half* W1 = (seg < NE) ? g_w1h + (size_t)seg * HID * DIM : g_sw1h;
    const __half* W3 = (seg < NE) ? g_w3h + (size_t)seg * HID * DIM : g_sw3h;
    const int n0 = blockIdx.x * BN;
    const int tid = threadIdx.x;

    int* stok = (int*)(smem + TOK_OFF);
    if (tid < BM) {
        int r = m0 + tid;
        int rr = (r < rows) ? r : m0;
        stok[tid] = (seg < NE) ? g_perm[segoff + rr] : rr;
    }
    __syncthreads();

    const __half* aptr[4];
    uint32_t boff[4], sdst[4];
#pragma unroll
    for (int i = 0; i < 4; i++) {
        int j = tid + i * 256;
        int r = j >> 3, c8 = j & 7;
        sdst[i] = SWZ(r, c8);
        aptr[i] = g_xh + (size_t)stok[r] * DIM + c8 * 8;
        int nn = n0 + r; if (nn >= HID) nn = HID - 1;
        boff[i] = (uint32_t)nn * DIM + c8 * 8;
    }
    auto loadAll = [&](const __half* W, int it, int buf) {
        const uint32_t base = sbase + buf * ST2;
        const int kt = it * BK;
#pragma unroll
        for (int i = 0; i < 4; i++) {
            cp16(base + sdst[i],          aptr[i] + kt);
            cp16(base + TILE_B + sdst[i], W + boff[i] + kt);
        }
    };

    const int lane = tid & 31, wid = tid >> 5;
    const int wm = wid & 1, wn = wid >> 1;
    const int g = lane >> 2, tg = lane & 3;

    const uint32_t a_roff = (uint32_t)(wm * 64 + (lane & 15)) * 128;
    const uint32_t a_x = lane & 7, a_c = (uint32_t)(lane >> 4);
    const uint32_t b_roff = (uint32_t)(wn * 32 + (lane & 7)) * 128;
    const uint32_t b_c = (uint32_t)((lane >> 3) & 1);

    float acc[4][4][4];
#pragma unroll
    for (int a = 0; a < 4; a++)
#pragma unroll
        for (int b = 0; b < 4; b++)
#pragma unroll
            for (int c = 0; c < 4; c++) acc[a][b][c] = 0.f;

    // stash addressing: per-thread private, uint32 value v at word [v*256 + tid]
    const uint32_t stash = sbase + STASH_OFF + tid * 4;

    // ---------------- loop 1: G = X W1^T ----------------
    loadAll(W1, 0, 0); cp_commit();
    for (int it = 0; it < NIT1; ++it) {
        const int buf = it & 1;
        if (it + 1 < NIT1) { loadAll(W1, it + 1, buf ^ 1); cp_commit(); cp_wait<1>(); }
        else               { cp_wait<0>(); }
        __syncthreads();
        const uint32_t aB = sbase + buf * ST2;
        const uint32_t bB = aB + TILE_B;
#pragma unroll
        for (int kk = 0; kk < 4; kk++) {
            const uint32_t ach = ((kk * 2 + a_c) ^ a_x) * 16;
            const uint32_t bch = ((kk * 2 + b_c) ^ a_x) * 16;
            uint32_t af[4][4];
#pragma unroll
            for (int mi = 0; mi < 4; mi++)
                ldm_x4(af[mi], aB + a_roff + mi * 2048 + ach);
#pragma unroll
            for (int ni = 0; ni < 4; ni++) {
                uint32_t bf[2];
                ldm_x2(bf, bB + b_roff + ni * 1024 + bch);
#pragma unroll
                for (int mi = 0; mi < 4; mi++) mma_f16(acc[mi][ni], af[mi], bf);
            }
        }
        __syncthreads();   // 2-stage: protect buf^1 before next-iter overwrite
    }

    // prime loop2's first tile BEFORE the stash epilogue (hides load latency)
    loadAll(W3, 0, 0); cp_commit();

    // epilogue 1: silu(G) -> SMEM stash (per-thread private; no barrier needed)
#pragma unroll
    for (int mi = 0; mi < 4; mi++)
#pragma unroll
        for (int ni = 0; ni < 4; ni++)
#pragma unroll
            for (int rh = 0; rh < 2; rh++) {
                float g0 = acc[mi][ni][rh * 2], g1 = acc[mi][ni][rh * 2 + 1];
                float s0 = g0 / (1.f + expf(-g0));
                float s1 = g1 / (1.f + expf(-g1));
                __half2 sv = __floats2half2_rn(s0, s1);
                const int v = (mi * 4 + ni) * 2 + rh;
                asm volatile("st.shared.b32 [%0], %1;" :: "r"(stash + v * 1024),
                             "r"(*(uint32_t*)&sv));
            }

#pragma unroll
    for (int a = 0; a < 4; a++)
#pragma unroll
        for (int b = 0; b < 4; b++)
#pragma unroll
            for (int c = 0; c < 4; c++) acc[a][b][c] = 0.f;

    // ---------------- loop 2: U = X W3^T ----------------
    for (int it = 0; it < NIT1; ++it) {
        const int buf = it & 1;
        if (it + 1 < NIT1) { loadAll(W3, it + 1, buf ^ 1); cp_commit(); cp_wait<1>(); }
        else               { cp_wait<0>(); }
        __syncthreads();
        const uint32_t aB = sbase + buf * ST2;
        const uint32_t bB = aB + TILE_B;
#pragma unroll
        for (int kk = 0; kk < 4; kk++) {
            const uint32_t ach = ((kk * 2 + a_c) ^ a_x) * 16;
            const uint32_t bch = ((kk * 2 + b_c) ^ a_x) * 16;
            uint32_t af[4][4];
#pragma unroll
            for (int mi = 0; mi < 4; mi++)
                ldm_x4(af[mi], aB + a_roff + mi * 2048 + ach);
#pragma unroll
            for (int ni = 0; ni < 4; ni++) {
                uint32_t bf[2];
                ldm_x2(bf, bB + b_roff + ni * 1024 + bch);
#pragma unroll
                for (int mi = 0; mi < 4; mi++) mma_f16(acc[mi][ni], af[mi], bf);
            }
        }
        __syncthreads();
    }

    // epilogue 2: h = stash(silu G) * U -> g_h (fp16)
#pragma unroll
    for (int mi = 0; mi < 4; mi++) {
#pragma unroll
        for (int rh = 0; rh < 2; rh++) {
            const int rr = m0 + wm * 64 + mi * 16 + g + rh * 8;
            if (rr >= rows) continue;
            __half* drow = g_h + (hbase + rr) * (size_t)HID;
#pragma unroll
            for (int ni = 0; ni < 4; ni++) {
                const int c = n0 + wn * 32 + ni * 8 + 2 * tg;
                if (c >= HID) continue;
                const int v = (mi * 4 + ni) * 2 + rh;
                uint32_t sbits;
                asm volatile("ld.shared.b32 %0, [%1];" : "=r"(sbits)
                             : "r"(stash + v * 1024));
                float2 sv = __half22float2(*(__half2*)&sbits);
                float h0 = sv.x * acc[mi][ni][rh * 2];
                float h1 = sv.y * acc[mi][ni][rh * 2 + 1];
                __half2 hv = __floats2half2_rn(h0, h1);
                *(uint32_t*)(drow + c) = *(uint32_t*)&hv;
            }
        }
    }
}

// ---------------- kernels 4/5: FFN2 — out (+)= coef * (h W2^T) --------------------------
template <bool SHARED>
__global__ __launch_bounds__(256, 2) void ffn2_kernel(float* __restrict__ out) {
    extern __shared__ char smem[];
    const uint32_t sbase = smem_u32(smem);
    const int z = SHARED ? NE : blockIdx.z;
    const int rows = SHARED ? T_TOK : g_counts[z];
    const int m0 = blockIdx.y * BM;
    if (m0 >= rows) return;
    const int segoff = SHARED ? 0 : g_offsets[z];
    const size_t hbase = SHARED ? (size_t)(T_TOK * TOPK) : (size_t)g_offsets[z];
    const __half* W2 = SHARED ? g_sw2h : g_w2h + (size_t)z * DIM * HID;
    const int n0 = blockIdx.x * BN;
    const int tid = threadIdx.x;

    const __half* aptr[4];
    const __half* bptr[4];
    uint32_t sdst[4];
#pragma unroll
    for (int i = 0; i < 4; i++) {
        int j = tid + i * 256;
        int r = j >> 3, c8 = j & 7;
        sdst[i] = SWZ(r, c8);
        int rr = (m0 + r < rows) ? (m0 + r) : m0;
        aptr[i] = g_h + (hbase + rr) * (size_t)HID + c8 * 8;
        bptr[i] = W2 + (size_t)(n0 + r) * HID + c8 * 8;
    }
    auto loadAll = [&](int it, int stg) {
        const uint32_t base = sbase + stg * ST2;
        const int kt = it * BK;
#pragma unroll
        for (int i = 0; i < 4; i++) {
            cp16(base + sdst[i],          aptr[i] + kt);
            cp16(base + TILE_B + sdst[i], bptr[i] + kt);
        }
    };

    const int lane = tid & 31, wid = tid >> 5;
    const int wm = wid & 1, wn = wid >> 1;
    const int g = lane >> 2, tg = lane & 3;

    const uint32_t a_roff = (uint32_t)(wm * 64 + (lane & 15)) * 128;
    const uint32_t a_x = lane & 7, a_c = (uint32_t)(lane >> 4);
    const uint32_t b_roff = (uint32_t)(wn * 32 + (lane & 7)) * 128;
    const uint32_t b_c = (uint32_t)((lane >> 3) & 1);

    float acc[4][4][4];
#pragma unroll
    for (int a = 0; a < 4; a++)
#pragma unroll
        for (int b = 0; b < 4; b++)
#pragma unroll
            for (int c = 0; c < 4; c++) acc[a][b][c] = 0.f;

    loadAll(0, 0); cp_commit();
    loadAll(1, 1); cp_commit();
    for (int it = 0; it < NIT2; ++it) {
        const int stg = it % 3;
        if (it + 1 < NIT2) cp_wait<1>(); else cp_wait<0>();
        __syncthreads();
        if (it + 2 < NIT2) { loadAll(it + 2, (it + 2) % 3); cp_commit(); }
        const uint32_t aB = sbase + stg * ST2;
        const uint32_t bB = aB + TILE_B;
#pragma unroll
        for (int kk = 0; kk < 4; kk++) {
            const uint32_t ach = ((kk * 2 + a_c) ^ a_x) * 16;
            const uint32_t bch = ((kk * 2 + b_c) ^ a_x) * 16;
            uint32_t af[4][4];
#pragma unroll
            for (int mi = 0; mi < 4; mi++)
                ldm_x4(af[mi], aB + a_roff + mi * 2048 + ach);
#pragma unroll
            for (int ni = 0; ni < 4; ni++) {
                uint32_t bf[2];
                ldm_x2(bf, bB + b_roff + ni * 1024 + bch);
#pragma unroll
                for (int mi = 0; mi < 4; mi++) mma_f16(acc[mi][ni], af[mi], bf);
            }
        }
    }

    // epilogue
#pragma unroll
    for (int mi = 0; mi < 4; mi++) {
#pragma unroll
        for (int rh = 0; rh < 2; rh++) {
            const int rr = m0 + wm * 64 + mi * 16 + g + rh * 8;
            if (!SHARED && rr >= rows) continue;
            const int   tok = SHARED ? rr : g_perm[segoff + rr];
            const float cf  = SHARED ? 1.f : g_coef[segoff + rr];
            float* orow = out + (size_t)tok * DIM;
#pragma unroll
            for (int ni = 0; ni < 4; ni++) {
                const int c = n0 + wn * 32 + ni * 8 + 2 * tg;
                if (SHARED) {
                    orow[c]     = acc[mi][ni][rh * 2];
                    orow[c + 1] = acc[mi][ni][rh * 2 + 1];
                } else {
                    atomicAdd(&orow[c],     cf * acc[mi][ni][rh * 2]);
                    atomicAdd(&orow[c + 1], cf * acc[mi][ni][rh * 2 + 1]);
                }
            }
        }
    }
}

// ---------------- launcher -------------------------------------------------------------------
extern "C" void kernel_launch(void* const* d_in, const int* in_sizes, int n_in,
                              void* d_out, int out_size) {
    const float* x   = (const float*)d_in[0];
    const float* gw  = (const float*)d_in[1];
    const float* w1  = (const float*)d_in[2];
    const float* w2  = (const float*)d_in[3];
    const float* w3  = (const float*)d_in[4];
    const float* sw1 = (const float*)d_in[5];
    const float* sw2 = (const float*)d_in[6];
    const float* sw3 = (const float*)d_in[7];
    float* out = (float*)d_out;

    cudaFuncSetAttribute(ffn1_kernel, cudaFuncAttributeMaxDynamicSharedMemorySize, SMEMF);
    cudaFuncSetAttribute(ffn2_kernel<true>,  cudaFuncAttributeMaxDynamicSharedMemorySize, SMEM2);
    cudaFuncSetAttribute(ffn2_kernel<false>, cudaFuncAttributeMaxDynamicSharedMemorySize, SMEM2);

    CvtArgs ca;
    void* p;
    cudaGetSymbolAddress(&p, g_xh);   ca.dst[0] = (uint2*)p; ca.src[0] = (const float4*)x;   ca.n4[0] = (T_TOK * DIM) / 4;
    cudaGetSymbolAddress(&p, g_w1h);  ca.dst[1] = (uint2*)p; ca.src[1] = (const float4*)w1;  ca.n4[1] = (NE * HID * DIM) / 4;
    cudaGetSymbolAddress(&p, g_w2h);  ca.dst[2] = (uint2*)p; ca.src[2] = (const float4*)w2;  ca.n4[2] = (NE * DIM * HID) / 4;
    cudaGetSymbolAddress(&p, g_w3h);  ca.dst[3] = (uint2*)p; ca.src[3] = (const float4*)w3;  ca.n4[3] = (NE * HID * DIM) / 4;
    cudaGetSymbolAddress(&p, g_sw1h); ca.dst[4] = (uint2*)p; ca.src[4] = (const float4*)sw1; ca.n4[4] = (HID * DIM) / 4;
    cudaGetSymbolAddress(&p, g_sw2h); ca.dst[5] = (uint2*)p; ca.src[5] = (const float4*)sw2; ca.n4[5] = (DIM * HID) / 4;
    cudaGetSymbolAddress(&p, g_sw3h); ca.dst[6] = (uint2*)p; ca.src[6] = (const float4*)sw3; ca.n4[6] = (HID * DIM) / 4;

    init_kernel<<<1, 32>>>();                                  // 1
    cvt_gate_kernel<<<GATE_BLKS + CVT_BLKS, 256>>>(ca, x, gw); // 2
    scatter_kernel<<<T_TOK / 256, 256>>>();                    // 3

    dim3 g1(NT1, T_TOK / BM, NE + 1);
    ffn1_kernel<<<g1, 256, SMEMF>>>();                         // 4
    dim3 g2s(NT2, T_TOK / BM, 1);
    ffn2_kernel<true><<<g2s, 256, SMEM2>>>(out);               // 5
    dim3 g2r(NT2, T_TOK / BM, NE);
    ffn2_kernel<false><<<g2r, 256, SMEM2>>>(out);              // 6
}